// round 3
// baseline (speedup 1.0000x reference)
#include <cuda_runtime.h>
#include <math.h>

#define MDL   4
#define CDIM  1000
#define NV4   250          // CDIM/4 float4 per row
#define NTHR  128          // 4 warps: warp m handles model m

// Device globals (no allocation allowed). Zero-initialized at module load;
// the last block of every launch restores them to zero -> deterministic replays.
__device__ double   g_acc[2];
__device__ unsigned g_count;

__global__ __launch_bounds__(NTHR) void cmcl_fused(
    const float* __restrict__ logits,        // (M, B, C) fp32
    const int*   __restrict__ t32,           // targets viewed as int32 words
    float* __restrict__ loss_out,            // scalar or null
    float* __restrict__ oracle,              // (B, C) or null
    float* __restrict__ idx_out,             // (B,)  or null
    int B)
{
    const int b    = blockIdx.x;
    const int warp = threadIdx.x >> 5;       // model index m
    const int lane = threadIdx.x & 31;

    __shared__ float s_ce[MDL];
    __shared__ float s_ent[MDL];
    __shared__ int   s_tgt;
    __shared__ int   s_win;

    // Row of model `warp`, sample `b`: 1000 contiguous floats, 16B-aligned.
    const float* __restrict__ row_f =
        logits + ((size_t)warp * (size_t)B + (size_t)b) * CDIM;
    const float4* __restrict__ row = (const float4*)row_f;

    // ---- issue the global reads for this lane's elements immediately ----
    float4 buf[8];
    #pragma unroll
    for (int k = 0; k < 8; k++) {
        int i = lane + 32 * k;
        if (i < NV4) buf[k] = __ldg(row + i);
    }

    // ---- thread 0: resolve target index (int64 vs int32 detection) ----
    if (threadIdx.x == 0) {
        // True int64 targets (< 1000, little-endian) have zero odd words.
        // 16 int32 words all matching that pattern by chance: p ~ 1e-48.
        int is64 = 1;
        #pragma unroll
        for (int k = 0; k < 16; k++)
            if (t32[2 * k + 1] != 0) { is64 = 0; break; }
        s_tgt = is64 ? t32[2 * b] : t32[b];
    }
    __syncthreads();
    const int tgt = s_tgt;

    // ---- pass 1: per-lane max, warp max ----
    float mx = -INFINITY;
    #pragma unroll
    for (int k = 0; k < 8; k++) {
        int i = lane + 32 * k;
        if (i < NV4)
            mx = fmaxf(mx, fmaxf(fmaxf(buf[k].x, buf[k].y),
                                 fmaxf(buf[k].z, buf[k].w)));
    }
    #pragma unroll
    for (int off = 16; off > 0; off >>= 1)
        mx = fmaxf(mx, __shfl_xor_sync(0xFFFFFFFFu, mx, off));

    // ---- pass 2: sum exp(x - mx) and plain sum (no per-element branching) ----
    float sexp = 0.0f, ssum = 0.0f;
    #pragma unroll
    for (int k = 0; k < 8; k++) {
        int i = lane + 32 * k;
        if (i < NV4) {
            ssum += (buf[k].x + buf[k].y) + (buf[k].z + buf[k].w);
            sexp += expf(buf[k].x - mx) + expf(buf[k].y - mx)
                  + expf(buf[k].z - mx) + expf(buf[k].w - mx);
        }
    }
    #pragma unroll
    for (int off = 16; off > 0; off >>= 1) {
        sexp += __shfl_xor_sync(0xFFFFFFFFu, sexp, off);
        ssum += __shfl_xor_sync(0xFFFFFFFFu, ssum, off);
    }

    if (lane == 0) {
        float tval = __ldg(row_f + tgt);                 // L1-hot
        float lse  = mx + logf(sexp);
        s_ce[warp]  = lse - tval;                                     // cross entropy
        s_ent[warp] = lse - ssum * (1.0f / CDIM) - logf((float)CDIM); // entropy term
    }
    __syncthreads();

    if (threadIdx.x == 0) {
        // winner = argmin_m (ce - ent); total_ent constant in m. Strict <:
        // first-min wins (jax argmin tie-break).
        float best = s_ce[0] - s_ent[0];
        int   win  = 0;
        float entsum = s_ent[0];
        #pragma unroll
        for (int m = 1; m < MDL; m++) {
            entsum += s_ent[m];
            float sc = s_ce[m] - s_ent[m];
            if (sc < best) { best = sc; win = m; }
        }
        s_win = win;
        if (idx_out) idx_out[b] = (float)win;
        atomicAdd(&g_acc[0], (double)(s_ce[win] - s_ent[win]));
        atomicAdd(&g_acc[1], (double)entsum);
    }
    __syncthreads();

    // ---- oracle row copy (source is L1-hot: this block just read it) ----
    if (oracle) {
        const float* __restrict__ src =
            logits + ((size_t)s_win * (size_t)B + (size_t)b) * CDIM;
        float* __restrict__ dst = oracle + (size_t)b * CDIM;  // 4B-aligned only
        for (int i = threadIdx.x; i < CDIM; i += NTHR)
            dst[i] = __ldg(src + i);
    }

    // ---- last block: finalize scalar loss and reset state for next replay ----
    if (threadIdx.x == 0) {
        __threadfence();
        unsigned t = atomicAdd(&g_count, 1u);
        if (t == (unsigned)gridDim.x - 1u) {
            double a0 = __longlong_as_double(
                atomicExch((unsigned long long*)&g_acc[0], 0ull));
            double a1 = __longlong_as_double(
                atomicExch((unsigned long long*)&g_acc[1], 0ull));
            if (loss_out) loss_out[0] = (float)((a0 + a1) / (double)B);
            g_count = 0u;          // reset for next graph replay
            __threadfence();
        }
    }
}

extern "C" void kernel_launch(void* const* d_in, const int* in_sizes, int n_in,
                              void* d_out, int out_size)
{
    const float* logits = (const float*)d_in[0];
    const int*   t32    = (const int*)d_in[1];
    const int B = in_sizes[1];                 // 8192

    float* out = (float*)d_out;
    const long long bc = (long long)B * CDIM;

    // Output layout: tuple (new_loss, oracle_logits, min_index) flattened.
    float* loss_p   = nullptr;
    float* oracle_p = nullptr;
    float* idx_p    = nullptr;
    long long osz = (long long)out_size;
    if (osz >= 1 + bc + B) {                   // full tuple
        loss_p   = out;
        oracle_p = out + 1;
        idx_p    = out + 1 + bc;
    } else if (osz == bc + B) {                // (oracle, idx)
        oracle_p = out;
        idx_p    = out + bc;
    } else if (osz == bc) {                    // oracle only
        oracle_p = out;
    } else if (osz == B) {                     // idx only
        idx_p = out;
    } else {                                   // scalar loss only
        loss_p = out;
    }

    cmcl_fused<<<B, NTHR>>>(logits, t32, loss_p, oracle_p, idx_p, B);
}